// round 2
// baseline (speedup 1.0000x reference)
#include <cuda_runtime.h>

// TemporalViewModel: 24-step GRU over 65536 independent sequences (F=32, H=32)
// + output projection (32 -> 16).
//
// fp32 SIMT, 2 sequences per thread packed into f32x2 lanes, sm_100+ packed
// fma.rn.f32x2 (SASS FFMA2). Weights pre-duplicated (w,w) into SMEM with a
// gate-interleaved [u][k][gate0..5] layout so each k-step is served by exactly
// 3 broadcast LDS.128 feeding 6 FFMA2s (FMA:LDS = 2:1).

#define TT   24
#define NSEQ 65536
#define NT   256   // threads per block

typedef unsigned long long u64;

__device__ __forceinline__ u64 pk(float lo, float hi){
    u64 r; asm("mov.b64 %0,{%1,%2};" : "=l"(r) : "f"(lo), "f"(hi)); return r;
}
__device__ __forceinline__ void upk(u64 v, float& lo, float& hi){
    asm("mov.b64 {%0,%1},%2;" : "=f"(lo), "=f"(hi) : "l"(v));
}
__device__ __forceinline__ void fma2(u64& d, u64 a, u64 b){
    asm("fma.rn.f32x2 %0,%1,%2,%0;" : "+l"(d) : "l"(a), "l"(b));
}

__device__ __forceinline__ float sigmf(float x){
    return __fdividef(1.0f, 1.0f + __expf(-x));
}
__device__ __forceinline__ float tanh_fast(float x){
    x = fminf(fmaxf(x, -15.0f), 15.0f);
    float e = __expf(2.0f * x);
    return (e - 1.0f) * __fdividef(1.0f, e + 1.0f);
}

// dynamic SMEM layout:
//   u64   sw[32*32*6]  duplicated weights, [u][k][gate]: 0..2 = W_ih(r,z,n), 3..5 = W_hh(r,z,n)
//   float sb[128]      biases: [0:32)=b_r sum, [32:64)=b_z sum, [64:96)=b_ih_n, [96:128)=b_hh_n
//   float swo[512]     output projection W (32x16)
//   u64   hnew[32*NT]  per-thread h staging
#define SMEM_BYTES (32*32*6*8 + 128*4 + 512*4 + NT*32*8)

extern "C" __global__ void __launch_bounds__(NT, 1)
gru_kernel(const float* __restrict__ spat, const float* __restrict__ met,
           const float* __restrict__ ctx,
           const float* __restrict__ W_ih, const float* __restrict__ W_hh,
           const float* __restrict__ b_ih, const float* __restrict__ b_hh,
           const float* __restrict__ Wo, float* __restrict__ out)
{
    extern __shared__ char smraw[];
    u64*   sw   = (u64*)smraw;                 // 49152 B
    float* sb   = (float*)(sw + 32*32*6);
    float* swo  = sb + 128;
    u64*   hnew = (u64*)(swo + 512);

    const int tid = threadIdx.x;

    // ---- prologue: stage duplicated, gate-interleaved weights in SMEM ----
    for (int i = tid; i < 3072; i += NT){
        int g = i >> 5, k = i & 31;
        int gate = g >> 5, u = g & 31;          // gate: 0=r,1=z,2=n ; u = hidden unit
        float wi = W_ih[i], wh = W_hh[i];
        sw[(u*32 + k)*6 + gate]     = pk(wi, wi);
        sw[(u*32 + k)*6 + 3 + gate] = pk(wh, wh);
    }
    for (int i = tid; i < 64; i += NT) sb[i] = b_ih[i] + b_hh[i];           // r,z combined bias
    for (int i = tid; i < 32; i += NT){ sb[64+i] = b_ih[64+i]; sb[96+i] = b_hh[64+i]; }
    for (int i = tid; i < 512; i += NT) swo[i] = Wo[i];
    __syncthreads();

    const int n0 = (blockIdx.x * NT + tid) * 2;   // this thread's first sequence

    u64 h[32];
    #pragma unroll
    for (int u = 0; u < 32; u++) h[u] = 0ULL;

    for (int t = 0; t < TT; t++){
        // ---- load + pack this timestep's features for both sequences ----
        u64 xp[32];
        {
            const float4* p = (const float4*)(spat + ((size_t)t*NSEQ + n0)*16);
            #pragma unroll
            for (int q = 0; q < 4; q++){
                float4 a = p[q], b = p[q+4];
                xp[q*4+0]=pk(a.x,b.x); xp[q*4+1]=pk(a.y,b.y);
                xp[q*4+2]=pk(a.z,b.z); xp[q*4+3]=pk(a.w,b.w);
            }
        }
        {
            const float4* p = (const float4*)(met + ((size_t)t*NSEQ + n0)*8);
            #pragma unroll
            for (int q = 0; q < 2; q++){
                float4 a = p[q], b = p[q+2];
                xp[16+q*4+0]=pk(a.x,b.x); xp[16+q*4+1]=pk(a.y,b.y);
                xp[16+q*4+2]=pk(a.z,b.z); xp[16+q*4+3]=pk(a.w,b.w);
            }
        }
        {
            const float4* p = (const float4*)(ctx + ((size_t)t*NSEQ + n0)*8);
            #pragma unroll
            for (int q = 0; q < 2; q++){
                float4 a = p[q], b = p[q+2];
                xp[24+q*4+0]=pk(a.x,b.x); xp[24+q*4+1]=pk(a.y,b.y);
                xp[24+q*4+2]=pk(a.z,b.z); xp[24+q*4+3]=pk(a.w,b.w);
            }
        }

        // ---- GRU cell: 32 hidden units ----
        #pragma unroll 1
        for (int u = 0; u < 32; u++){
            const u64* wu = sw + u*192;   // 32 k-steps x 6 gates
            u64 arx=0, azx=0, anx=0, arh=0, azh=0, anh=0;
            #pragma unroll
            for (int k = 0; k < 32; k++){
                u64 xk = xp[k], hk = h[k];
                ulonglong2 A = *(const ulonglong2*)(wu + k*6 + 0);
                ulonglong2 B = *(const ulonglong2*)(wu + k*6 + 2);
                ulonglong2 C = *(const ulonglong2*)(wu + k*6 + 4);
                fma2(arx, xk, A.x);
                fma2(azx, xk, A.y);
                fma2(anx, xk, B.x);
                fma2(arh, hk, B.y);
                fma2(azh, hk, C.x);
                fma2(anh, hk, C.y);
            }
            float br = sb[u], bz = sb[32+u], bin = sb[64+u], bhn = sb[96+u];
            float rx0,rx1,rh0,rh1,zx0,zx1,zh0,zh1,nx0,nx1,nh0,nh1,h0,h1;
            upk(arx,rx0,rx1); upk(arh,rh0,rh1);
            upk(azx,zx0,zx1); upk(azh,zh0,zh1);
            upk(anx,nx0,nx1); upk(anh,nh0,nh1);
            upk(h[u],h0,h1);
            float r0 = sigmf(rx0+rh0+br), r1 = sigmf(rx1+rh1+br);
            float z0 = sigmf(zx0+zh0+bz), z1 = sigmf(zx1+zh1+bz);
            float nn0 = tanh_fast(nx0 + bin + r0*(nh0 + bhn));
            float nn1 = tanh_fast(nx1 + bin + r1*(nh1 + bhn));
            float hn0 = nn0 + z0*(h0 - nn0);   // (1-z)*n + z*h
            float hn1 = nn1 + z1*(h1 - nn1);
            hnew[u*NT + tid] = pk(hn0, hn1);
        }
        #pragma unroll
        for (int u = 0; u < 32; u++) h[u] = hnew[u*NT + tid];
    }

    // ---- output projection: out = h @ W  (32 -> 16) ----
    float hf0[32], hf1[32];
    #pragma unroll
    for (int u = 0; u < 32; u++) upk(h[u], hf0[u], hf1[u]);
    #pragma unroll
    for (int s = 0; s < 16; s++){
        float a0 = 0.f, a1 = 0.f;
        #pragma unroll
        for (int u = 0; u < 32; u++){
            float w = swo[u*16 + s];
            a0 += hf0[u] * w;
            a1 += hf1[u] * w;
        }
        out[(size_t)n0*16 + s]     = a0;
        out[(size_t)(n0+1)*16 + s] = a1;
    }
}

extern "C" void kernel_launch(void* const* d_in, const int* in_sizes, int n_in,
                              void* d_out, int out_size)
{
    const float* spat = (const float*)d_in[0];
    const float* met  = (const float*)d_in[1];
    const float* ctx  = (const float*)d_in[2];
    const float* W_ih = (const float*)d_in[3];
    const float* W_hh = (const float*)d_in[4];
    const float* b_ih = (const float*)d_in[5];
    const float* b_hh = (const float*)d_in[6];
    const float* Wo   = (const float*)d_in[7];
    float* out = (float*)d_out;

    cudaFuncSetAttribute(gru_kernel, cudaFuncAttributeMaxDynamicSharedMemorySize, SMEM_BYTES);
    dim3 grid(NSEQ / (2 * NT));   // 128 CTAs x 256 threads, 2 sequences/thread
    gru_kernel<<<grid, NT, SMEM_BYTES>>>(spat, met, ctx, W_ih, W_hh, b_ih, b_hh, Wo, out);
}

// round 3
// speedup vs baseline: 1.0029x; 1.0029x over previous
#include <cuda_runtime.h>

// TemporalViewModel: 24-step GRU over 65536 independent sequences (F=32, H=32)
// + output projection (32 -> 16).
//
// fp32 SIMT, 2 sequences per thread packed into f32x2 lanes, sm_100+ packed
// fma.rn.f32x2 (SASS FFMA2). Weights pre-duplicated (w,w) into SMEM with a
// gate-interleaved [u][k][gate0..5] layout so each k-step is served by exactly
// 3 broadcast LDS.128 feeding 6 FFMA2s (FMA:LDS = 2:1).

#define TT   24
#define NSEQ 65536
#define NT   256   // threads per block

typedef unsigned long long u64;

__device__ __forceinline__ u64 pk(float lo, float hi){
    u64 r; asm("mov.b64 %0,{%1,%2};" : "=l"(r) : "f"(lo), "f"(hi)); return r;
}
__device__ __forceinline__ void upk(u64 v, float& lo, float& hi){
    asm("mov.b64 {%0,%1},%2;" : "=f"(lo), "=f"(hi) : "l"(v));
}
__device__ __forceinline__ void fma2(u64& d, u64 a, u64 b){
    asm("fma.rn.f32x2 %0,%1,%2,%0;" : "+l"(d) : "l"(a), "l"(b));
}

__device__ __forceinline__ float sigmf(float x){
    return __fdividef(1.0f, 1.0f + __expf(-x));
}
__device__ __forceinline__ float tanh_fast(float x){
    x = fminf(fmaxf(x, -15.0f), 15.0f);
    float e = __expf(2.0f * x);
    return (e - 1.0f) * __fdividef(1.0f, e + 1.0f);
}

// dynamic SMEM layout:
//   u64   sw[32*32*6]  duplicated weights, [u][k][gate]: 0..2 = W_ih(r,z,n), 3..5 = W_hh(r,z,n)
//   float sb[128]      biases: [0:32)=b_r sum, [32:64)=b_z sum, [64:96)=b_ih_n, [96:128)=b_hh_n
//   float swo[512]     output projection W (32x16)
//   u64   hnew[32*NT]  per-thread h staging
#define SMEM_BYTES (32*32*6*8 + 128*4 + 512*4 + NT*32*8)

extern "C" __global__ void __launch_bounds__(NT, 1)
gru_kernel(const float* __restrict__ spat, const float* __restrict__ met,
           const float* __restrict__ ctx,
           const float* __restrict__ W_ih, const float* __restrict__ W_hh,
           const float* __restrict__ b_ih, const float* __restrict__ b_hh,
           const float* __restrict__ Wo, float* __restrict__ out)
{
    extern __shared__ char smraw[];
    u64*   sw   = (u64*)smraw;                 // 49152 B
    float* sb   = (float*)(sw + 32*32*6);
    float* swo  = sb + 128;
    u64*   hnew = (u64*)(swo + 512);

    const int tid = threadIdx.x;

    // ---- prologue: stage duplicated, gate-interleaved weights in SMEM ----
    for (int i = tid; i < 3072; i += NT){
        int g = i >> 5, k = i & 31;
        int gate = g >> 5, u = g & 31;          // gate: 0=r,1=z,2=n ; u = hidden unit
        float wi = W_ih[i], wh = W_hh[i];
        sw[(u*32 + k)*6 + gate]     = pk(wi, wi);
        sw[(u*32 + k)*6 + 3 + gate] = pk(wh, wh);
    }
    for (int i = tid; i < 64; i += NT) sb[i] = b_ih[i] + b_hh[i];           // r,z combined bias
    for (int i = tid; i < 32; i += NT){ sb[64+i] = b_ih[64+i]; sb[96+i] = b_hh[64+i]; }
    for (int i = tid; i < 512; i += NT) swo[i] = Wo[i];
    __syncthreads();

    const int n0 = (blockIdx.x * NT + tid) * 2;   // this thread's first sequence

    u64 h[32];
    #pragma unroll
    for (int u = 0; u < 32; u++) h[u] = 0ULL;

    for (int t = 0; t < TT; t++){
        // ---- load + pack this timestep's features for both sequences ----
        u64 xp[32];
        {
            const float4* p = (const float4*)(spat + ((size_t)t*NSEQ + n0)*16);
            #pragma unroll
            for (int q = 0; q < 4; q++){
                float4 a = p[q], b = p[q+4];
                xp[q*4+0]=pk(a.x,b.x); xp[q*4+1]=pk(a.y,b.y);
                xp[q*4+2]=pk(a.z,b.z); xp[q*4+3]=pk(a.w,b.w);
            }
        }
        {
            const float4* p = (const float4*)(met + ((size_t)t*NSEQ + n0)*8);
            #pragma unroll
            for (int q = 0; q < 2; q++){
                float4 a = p[q], b = p[q+2];
                xp[16+q*4+0]=pk(a.x,b.x); xp[16+q*4+1]=pk(a.y,b.y);
                xp[16+q*4+2]=pk(a.z,b.z); xp[16+q*4+3]=pk(a.w,b.w);
            }
        }
        {
            const float4* p = (const float4*)(ctx + ((size_t)t*NSEQ + n0)*8);
            #pragma unroll
            for (int q = 0; q < 2; q++){
                float4 a = p[q], b = p[q+2];
                xp[24+q*4+0]=pk(a.x,b.x); xp[24+q*4+1]=pk(a.y,b.y);
                xp[24+q*4+2]=pk(a.z,b.z); xp[24+q*4+3]=pk(a.w,b.w);
            }
        }

        // ---- GRU cell: 32 hidden units ----
        #pragma unroll 1
        for (int u = 0; u < 32; u++){
            const u64* wu = sw + u*192;   // 32 k-steps x 6 gates
            u64 arx=0, azx=0, anx=0, arh=0, azh=0, anh=0;
            #pragma unroll
            for (int k = 0; k < 32; k++){
                u64 xk = xp[k], hk = h[k];
                ulonglong2 A = *(const ulonglong2*)(wu + k*6 + 0);
                ulonglong2 B = *(const ulonglong2*)(wu + k*6 + 2);
                ulonglong2 C = *(const ulonglong2*)(wu + k*6 + 4);
                fma2(arx, xk, A.x);
                fma2(azx, xk, A.y);
                fma2(anx, xk, B.x);
                fma2(arh, hk, B.y);
                fma2(azh, hk, C.x);
                fma2(anh, hk, C.y);
            }
            float br = sb[u], bz = sb[32+u], bin = sb[64+u], bhn = sb[96+u];
            float rx0,rx1,rh0,rh1,zx0,zx1,zh0,zh1,nx0,nx1,nh0,nh1,h0,h1;
            upk(arx,rx0,rx1); upk(arh,rh0,rh1);
            upk(azx,zx0,zx1); upk(azh,zh0,zh1);
            upk(anx,nx0,nx1); upk(anh,nh0,nh1);
            upk(h[u],h0,h1);
            float r0 = sigmf(rx0+rh0+br), r1 = sigmf(rx1+rh1+br);
            float z0 = sigmf(zx0+zh0+bz), z1 = sigmf(zx1+zh1+bz);
            float nn0 = tanh_fast(nx0 + bin + r0*(nh0 + bhn));
            float nn1 = tanh_fast(nx1 + bin + r1*(nh1 + bhn));
            float hn0 = nn0 + z0*(h0 - nn0);   // (1-z)*n + z*h
            float hn1 = nn1 + z1*(h1 - nn1);
            hnew[u*NT + tid] = pk(hn0, hn1);
        }
        #pragma unroll
        for (int u = 0; u < 32; u++) h[u] = hnew[u*NT + tid];
    }

    // ---- output projection: out = h @ W  (32 -> 16) ----
    float hf0[32], hf1[32];
    #pragma unroll
    for (int u = 0; u < 32; u++) upk(h[u], hf0[u], hf1[u]);
    #pragma unroll
    for (int s = 0; s < 16; s++){
        float a0 = 0.f, a1 = 0.f;
        #pragma unroll
        for (int u = 0; u < 32; u++){
            float w = swo[u*16 + s];
            a0 += hf0[u] * w;
            a1 += hf1[u] * w;
        }
        out[(size_t)n0*16 + s]     = a0;
        out[(size_t)(n0+1)*16 + s] = a1;
    }
}

extern "C" void kernel_launch(void* const* d_in, const int* in_sizes, int n_in,
                              void* d_out, int out_size)
{
    const float* spat = (const float*)d_in[0];
    const float* met  = (const float*)d_in[1];
    const float* ctx  = (const float*)d_in[2];
    const float* W_ih = (const float*)d_in[3];
    const float* W_hh = (const float*)d_in[4];
    const float* b_ih = (const float*)d_in[5];
    const float* b_hh = (const float*)d_in[6];
    const float* Wo   = (const float*)d_in[7];
    float* out = (float*)d_out;

    cudaFuncSetAttribute(gru_kernel, cudaFuncAttributeMaxDynamicSharedMemorySize, SMEM_BYTES);
    dim3 grid(NSEQ / (2 * NT));   // 128 CTAs x 256 threads, 2 sequences/thread
    gru_kernel<<<grid, NT, SMEM_BYTES>>>(spat, met, ctx, W_ih, W_hh, b_ih, b_hh, Wo, out);
}